// round 11
// baseline (speedup 1.0000x reference)
#include <cuda_runtime.h>
#include <math.h>

#define NCH 16
#define NB 5
#define MAXN 20000
#define MAXE 640000

// Scratch (allocation-free: __device__ globals; zero-initialized at module load)
__device__ int g_counts[MAXN];
__device__ int g_row[MAXN + 1];
__device__ int g_rank[MAXE];
__device__ float4 g_rec[MAXE];    // sorted: {ex, ey, ez, sender_bits}

// Histogram + per-edge rank in one pass. Requires g_counts == 0 on entry
// (true at load; k_scan re-zeroes after reading each call).
__global__ void k_hist(const int* __restrict__ recv, int E) {
    int i = blockIdx.x * blockDim.x + threadIdx.x;
    if (i < E) g_rank[i] = atomicAdd(&g_counts[recv[i]], 1);
}

// Single-block scan: thread-serial ITEMS + shfl warp scan + warp-totals scan.
// Also re-zeroes g_counts for the next kernel_launch call.
__global__ void k_scan(int n) {
    const int T = 1024;
    const int ITEMS = 20;
    int tid = threadIdx.x;
    int lane = tid & 31, wid = tid >> 5;
    int start = tid * ITEMS;

    int loc[ITEMS];
    int sum = 0;
    #pragma unroll
    for (int k = 0; k < ITEMS; k++) {
        int i = start + k;
        int v = (i < n) ? g_counts[i] : 0;
        loc[k] = sum;
        sum += v;
    }
    int s = sum;
    #pragma unroll
    for (int off = 1; off < 32; off <<= 1) {
        int t = __shfl_up_sync(0xffffffffu, s, off);
        if (lane >= off) s += t;
    }
    __shared__ int wsum[32];
    if (lane == 31) wsum[wid] = s;
    __syncthreads();
    if (wid == 0) {
        int w = wsum[lane];
        #pragma unroll
        for (int off = 1; off < 32; off <<= 1) {
            int t = __shfl_up_sync(0xffffffffu, w, off);
            if (lane >= off) w += t;
        }
        wsum[lane] = w;
    }
    __syncthreads();
    int base = (wid > 0 ? wsum[wid - 1] : 0) + (s - sum);
    #pragma unroll
    for (int k = 0; k < ITEMS; k++) {
        int i = start + k;
        if (i < n) { g_row[i] = base + loc[k]; g_counts[i] = 0; }
    }
    if (tid == T - 1) g_row[n] = wsum[31];
}

// Atomic-free scatter: ONE scattered 16-byte store per edge.
__global__ void k_scatter(const int* __restrict__ recv,
                          const int* __restrict__ senders,
                          const float* __restrict__ edges, int E) {
    int i = blockIdx.x * blockDim.x + threadIdx.x;
    if (i >= E) return;
    int pos = g_row[recv[i]] + g_rank[i];
    float ex = edges[3 * i + 0];
    float ey = edges[3 * i + 1];
    float ez = edges[3 * i + 2];
    g_rec[pos] = make_float4(ex, ey, ez, __int_as_float(senders[i]));
}

// Radial + tensor-product body for one edge. `valid` constant-folds to
// unguarded code in the full loop; real predicate only in the tail.
#define EDGE_BODY(rec, n0v, n1x, n1y, n1z, valid)                              \
{                                                                              \
    float ex = (rec).x, ey = (rec).y, ez = (rec).z;                            \
    float r2 = fmaf(ex, ex, fmaf(ey, ey, ez * ez));                            \
    float r  = sqrtf(r2);                                                      \
    float E0 = __expf(-0.7f * r2);                                             \
    float tt = __expf(1.225f * r);                                             \
    float q1 = E0 * tt, q2 = q1 * tt, q3 = q2 * tt, q4 = q3 * tt;              \
    float rad00 = fmaf(q4, a00[4], fmaf(q3, a00[3], fmaf(q2, a00[2], fmaf(q1, a00[1], E0 * a00[0])))); \
    float rad01 = fmaf(q4, a01[4], fmaf(q3, a01[3], fmaf(q2, a01[2], fmaf(q1, a01[1], E0 * a01[0])))); \
    float rad10 = fmaf(q4, a10[4], fmaf(q3, a10[3], fmaf(q2, a10[2], fmaf(q1, a10[1], E0 * a10[0])))); \
    float rad11 = fmaf(q4, a11[4], fmaf(q3, a11[3], fmaf(q2, a11[2], fmaf(q1, a11[1], E0 * a11[0])))); \
    if (valid) {                                                               \
        m0a = fmaf(n0v, rad00, m0a);                                           \
        float dot11 = fmaf(n1x, ey, fmaf(n1y, ez, n1z * ex));                  \
        m0b = fmaf(W110f * rad11, dot11, m0b);                                 \
        float t01 = (n0v) * rad01;                                             \
        m1a0 = fmaf(t01, ey, m1a0);                                            \
        m1a1 = fmaf(t01, ez, m1a1);                                            \
        m1a2 = fmaf(t01, ex, m1a2);                                            \
        m1b0 = fmaf(rad10, n1x, m1b0);                                         \
        m1b1 = fmaf(rad10, n1y, m1b1);                                         \
        m1b2 = fmaf(rad10, n1z, m1b2);                                         \
        float t11 = W111f * rad11;                                             \
        m1c0 = fmaf(t11, (n1y) * ex - (n1z) * ez, m1c0);                       \
        m1c1 = fmaf(t11, (n1z) * ey - (n1x) * ex, m1c1);                       \
        m1c2 = fmaf(t11, (n1x) * ez - (n1y) * ey, m1c2);                       \
    }                                                                          \
}

// Main gather: grid-stride NODE loop per warp, preamble paid once per warp.
// lane = (half<<4)|channel, 4 edges per iteration, 1-deep rec pipeline.
// Full iterations are completely unguarded; remainder handled in a tail.
__global__ void __launch_bounds__(256, 4) k_main(
    const float* __restrict__ nodes0, const float* __restrict__ nodes1,
    const float* __restrict__ c00, const float* __restrict__ c01,
    const float* __restrict__ c10, const float* __restrict__ c11,
    const float* __restrict__ w000, const float* __restrict__ w011,
    const float* __restrict__ w101, const float* __restrict__ w110,
    const float* __restrict__ w111,
    float* __restrict__ out0, float* __restrict__ out1, int n_nodes)
{
    int gwarp = (blockIdx.x * blockDim.x + threadIdx.x) >> 5;
    int nwarps = (gridDim.x * blockDim.x) >> 5;
    int lane = threadIdx.x & 31;
    int c = lane & 15;
    int half = lane >> 4;

    // Radial coefficients: RBF constants K_k AND path weights pre-folded.
    const float Kf[NB] = {
        1.0f,
        (float)exp(-0.7 * 0.875 * 0.875),
        (float)exp(-0.7 * 1.75  * 1.75),
        (float)exp(-0.7 * 2.625 * 2.625),
        (float)exp(-0.7 * 3.5   * 3.5)
    };
    const float Y00 = 0.28209479177387814f;
    const float Y1C = 0.4886025119029199f;
    float W000f = w000[c] * Y00;
    float W011f = w011[c] * Y1C;
    float W101f = w101[c] * Y00;
    float W110f = w110[c] * 0.57735026918962576f * Y1C;  // 1/sqrt(3) * Y1C
    float W111f = w111[c] * 0.70710678118654752f * Y1C;  // 1/sqrt(2) * Y1C

    float a00[NB], a01[NB], a10[NB], a11[NB];
    #pragma unroll
    for (int k = 0; k < NB; k++) {
        a00[k] = c00[c * NB + k] * Kf[k] * W000f;   // rad00 pre-weighted
        a01[k] = c01[c * NB + k] * Kf[k] * W011f;   // rad01 pre-weighted
        a10[k] = c10[c * NB + k] * Kf[k] * W101f;   // rad10 pre-weighted
        a11[k] = c11[c * NB + k] * Kf[k];           // rad11 raw (two weights)
    }

    for (int node = gwarp; node < n_nodes; node += nwarps) {
        int rs = g_row[node];
        int re = g_row[node + 1];

        float m0a = 0.f, m0b = 0.f;
        float m1a0 = 0.f, m1a1 = 0.f, m1a2 = 0.f;
        float m1b0 = 0.f, m1b1 = 0.f, m1b2 = 0.f;
        float m1c0 = 0.f, m1c1 = 0.f, m1c2 = 0.f;

        if (rs < re) {
            int last = re - 1;
            // Pipeline prologue (indices clamped to the segment).
            int i0 = rs + half;     if (i0 > last) i0 = last;
            int i1 = rs + 2 + half; if (i1 > last) i1 = last;
            float4 rec0 = g_rec[i0];
            float4 rec1 = g_rec[i1];

            int base = rs;
            #pragma unroll 1
            for (; base + 4 <= re; base += 4) {
                // Node gathers for CURRENT edges — senders already in regs.
                int s0 = __float_as_int(rec0.w);
                int s1 = __float_as_int(rec1.w);
                float n0v0 = nodes0[s0 * NCH + c];
                float n0v1 = nodes0[s1 * NCH + c];
                const float* p0 = nodes1 + (s0 * NCH + c) * 3;
                const float* p1 = nodes1 + (s1 * NCH + c) * 3;
                float n1x0 = p0[0], n1y0 = p0[1], n1z0 = p0[2];
                float n1x1 = p1[0], n1y1 = p1[1], n1z1 = p1[2];

                // Prefetch NEXT group's recs (clamped — 1 IMNMX each).
                int j0 = base + 4 + half;  if (j0 > last) j0 = last;
                int j1 = base + 6 + half;  if (j1 > last) j1 = last;
                float4 nrec0 = g_rec[j0];
                float4 nrec1 = g_rec[j1];

                EDGE_BODY(rec0, n0v0, n1x0, n1y0, n1z0, true);
                EDGE_BODY(rec1, n0v1, n1x1, n1y1, n1z1, true);

                rec0 = nrec0; rec1 = nrec1;
            }

            // Tail: 1..3 leftover edges, recs already prefetched.
            if (base < re) {
                bool v0 = (base + half) < re;
                bool v1 = (base + 2 + half) < re;
                int s0 = __float_as_int(rec0.w);
                int s1 = __float_as_int(rec1.w);
                float n0v0 = nodes0[s0 * NCH + c];
                float n0v1 = nodes0[s1 * NCH + c];
                const float* p0 = nodes1 + (s0 * NCH + c) * 3;
                const float* p1 = nodes1 + (s1 * NCH + c) * 3;
                float n1x0 = p0[0], n1y0 = p0[1], n1z0 = p0[2];
                float n1x1 = p1[0], n1y1 = p1[1], n1z1 = p1[2];

                EDGE_BODY(rec0, n0v0, n1x0, n1y0, n1z0, v0);
                EDGE_BODY(rec1, n0v1, n1x1, n1y1, n1z1, v1);
            }
        }

        // Combine the two half-warps and store this node's outputs.
        const unsigned FULL = 0xffffffffu;
        m0a  += __shfl_xor_sync(FULL, m0a, 16);
        m0b  += __shfl_xor_sync(FULL, m0b, 16);
        m1a0 += __shfl_xor_sync(FULL, m1a0, 16);
        m1a1 += __shfl_xor_sync(FULL, m1a1, 16);
        m1a2 += __shfl_xor_sync(FULL, m1a2, 16);
        m1b0 += __shfl_xor_sync(FULL, m1b0, 16);
        m1b1 += __shfl_xor_sync(FULL, m1b1, 16);
        m1b2 += __shfl_xor_sync(FULL, m1b2, 16);
        m1c0 += __shfl_xor_sync(FULL, m1c0, 16);
        m1c1 += __shfl_xor_sync(FULL, m1c1, 16);
        m1c2 += __shfl_xor_sync(FULL, m1c2, 16);

        if (half == 0) {
            out0[node * 32 + c]      = m0a;
            out0[node * 32 + 16 + c] = m0b;
            float* oa = out1 + (node * 48 + c) * 3;
            oa[0] = m1a0; oa[1] = m1a1; oa[2] = m1a2;
            float* ob = out1 + (node * 48 + 16 + c) * 3;
            ob[0] = m1b0; ob[1] = m1b1; ob[2] = m1b2;
            float* oc = out1 + (node * 48 + 32 + c) * 3;
            oc[0] = m1c0; oc[1] = m1c1; oc[2] = m1c2;
        }
    }
}

extern "C" void kernel_launch(void* const* d_in, const int* in_sizes, int n_in,
                              void* d_out, int out_size) {
    const float* coords  = (const float*)d_in[0];
    const float* nodes0  = (const float*)d_in[1];
    const float* nodes1  = (const float*)d_in[2];
    const float* edges   = (const float*)d_in[3];
    const int*   senders = (const int*)d_in[4];
    const int*   recv    = (const int*)d_in[5];
    const float* c00 = (const float*)d_in[6];
    const float* c01 = (const float*)d_in[7];
    const float* c10 = (const float*)d_in[8];
    const float* c11 = (const float*)d_in[9];
    const float* w000 = (const float*)d_in[10];
    const float* w011 = (const float*)d_in[11];
    const float* w101 = (const float*)d_in[12];
    const float* w110 = (const float*)d_in[13];
    const float* w111 = (const float*)d_in[14];
    float* out = (float*)d_out;

    int N = in_sizes[0] / 3;
    int E = in_sizes[3] / 3;

    cudaMemcpyAsync(out, coords, (size_t)3 * N * sizeof(float),
                    cudaMemcpyDeviceToDevice);
    float* out0 = out + (size_t)3 * N;
    float* out1 = out0 + (size_t)32 * N;

    k_hist<<<(E + 255) / 256, 256>>>(recv, E);
    k_scan<<<1, 1024>>>(N);
    k_scatter<<<(E + 255) / 256, 256>>>(recv, senders, edges, E);
    // Full-residency grid: 592 blocks x 8 warps = 4736 warps
    // (32 warps/SM x 148 SMs); each warp walks ~4.2 nodes.
    k_main<<<592, 256>>>(nodes0, nodes1,
                         c00, c01, c10, c11,
                         w000, w011, w101, w110, w111,
                         out0, out1, N);
}